// round 10
// baseline (speedup 1.0000x reference)
#include <cuda_runtime.h>
#include <cuda_bf16.h>
#include <cuda_fp16.h>
#include <math.h>
#include <stdint.h>

// Problem constants
#define S_ 2
#define B_ 2048
#define D_ 1024
#define H_ 2048
#define E_ 8
#define O_ 1024
#define T_ (S_*B_)        // 4096 tokens
#define P_ (T_*2)         // 8192 (token, k) pairs
#define MAXR 4096
#define OUT_OFF ((size_t)B_*O_)

// ---------------- scratch (device globals) ----------------
__device__ __align__(128) __half g_xh[(size_t)T_ * D_];
__device__ __align__(128) __half g_w1h[(size_t)E_ * H_ * D_];
__device__ __align__(128) __half g_w2h[(size_t)E_ * H_ * H_];
__device__ __align__(128) __half g_fwh[(size_t)O_ * H_];
__device__ __align__(128) __half g_Hh[(size_t)P_ * H_];
__device__ __align__(128) float  g_Y[(size_t)P_ * H_];
__device__ __align__(128) __half g_ch[(size_t)B_ * H_];
__device__ __align__(128) float g_gate[P_];
__device__ __align__(128) int   g_list[E_ * MAXR];
__device__ int   g_cnt[E_];

__device__ __forceinline__ uint32_t smem_u32(const void* p) {
    uint32_t a;
    asm("{ .reg .u64 t; cvta.to.shared.u64 t, %1; cvt.u32.u64 %0, t; }" : "=r"(a) : "l"(p));
    return a;
}

#define LDSM4(r0, r1, r2, r3, addr) \
    asm volatile("ldmatrix.sync.aligned.m8n8.x4.shared.b16 {%0,%1,%2,%3}, [%4];" \
        : "=r"(r0), "=r"(r1), "=r"(r2), "=r"(r3) : "r"(addr))

#define MMA16816(d, a, b) \
    asm volatile("mma.sync.aligned.m16n8k16.row.col.f32.f16.f16.f32 " \
        "{%0,%1,%2,%3}, {%4,%5,%6,%7}, {%8,%9}, {%0,%1,%2,%3};" \
        : "+f"((d)[0]), "+f"((d)[1]), "+f"((d)[2]), "+f"((d)[3]) \
        : "r"((a)[0]), "r"((a)[1]), "r"((a)[2]), "r"((a)[3]), \
          "r"((b)[0]), "r"((b)[1]))

#define CPA16(dst, src, sz) \
    asm volatile("cp.async.cg.shared.global [%0], [%1], 16, %2;" \
        :: "r"(dst), "l"(src), "r"(sz) : "memory")
#define CPCOMMIT() asm volatile("cp.async.commit_group;" ::: "memory")
#define CPWAIT(n)  asm volatile("cp.async.wait_group %0;" :: "n"(n) : "memory")

// swizzled byte offset within an N-row x 32-col fp16 plane (64B rows, 4x16B chunks)
__device__ __forceinline__ int swoff(int r, int c) {
    return r * 64 + ((c ^ ((r >> 1) & 3)) << 4);
}

__global__ void zero_kernel() {
    if (threadIdx.x < E_) g_cnt[threadIdx.x] = 0;
}

// ---------------- pack fp32 -> fp16 ----------------
__global__ void pack_half(const float* __restrict__ src,
                          __half* __restrict__ dst, int n4) {
    int i = blockIdx.x * blockDim.x + threadIdx.x;
    if (i >= n4) return;
    float4 v = reinterpret_cast<const float4*>(src)[i];
    __half2 a = __floats2half2_rn(v.x, v.y);
    __half2 b = __floats2half2_rn(v.z, v.w);
    uint2 o;
    o.x = *reinterpret_cast<uint32_t*>(&a);
    o.y = *reinterpret_cast<uint32_t*>(&b);
    reinterpret_cast<uint2*>(dst)[i] = o;
}

// ---------------- gating ----------------
__global__ __launch_bounds__(256) void gating_kernel(
        const float* __restrict__ xs, const float* __restrict__ Wg,
        const float* __restrict__ bias, float* __restrict__ out)
{
    __shared__ __align__(16) float ws[E_][D_];
    int tid = threadIdx.x;
    for (int i = tid; i < E_*D_; i += 256) {
        int e = i >> 10, d = i & (D_-1);
        ws[e][d] = Wg[d*E_ + e];
    }
    __syncthreads();
    int warp = tid >> 5, lane = tid & 31;
    for (int tt = 0; tt < 8; ++tt) {
        int t = blockIdx.x * 64 + warp * 8 + tt;
        float acc[E_];
        #pragma unroll
        for (int e = 0; e < E_; ++e) acc[e] = 0.f;
        const float4* xrow = reinterpret_cast<const float4*>(xs + (size_t)t * D_);
        #pragma unroll
        for (int it = 0; it < D_/128; ++it) {
            float4 x = xrow[lane + it*32];
            #pragma unroll
            for (int e = 0; e < E_; ++e) {
                float4 w = reinterpret_cast<const float4*>(ws[e])[lane + it*32];
                acc[e] += x.x*w.x + x.y*w.y + x.z*w.z + x.w*w.w;
            }
        }
        #pragma unroll
        for (int off = 16; off > 0; off >>= 1) {
            #pragma unroll
            for (int e = 0; e < E_; ++e)
                acc[e] += __shfl_xor_sync(0xffffffffu, acc[e], off);
        }
        if (lane == 0) {
            float h[E_];
            #pragma unroll
            for (int e = 0; e < E_; ++e) h[e] = acc[e] + bias[e];
            float m1 = h[0]; int i1 = 0;
            #pragma unroll
            for (int e = 1; e < E_; ++e) if (h[e] > m1) { m1 = h[e]; i1 = e; }
            float m2 = -3.0e38f; int i2 = 0;
            #pragma unroll
            for (int e = 0; e < E_; ++e) if (e != i1 && h[e] > m2) { m2 = h[e]; i2 = e; }
            float pr[E_]; float den = 0.f;
            #pragma unroll
            for (int e = 0; e < E_; ++e) { pr[e] = expf(h[e] - m1); den += pr[e]; }
            float inv = 1.f / den;
            float* ep = out + OUT_OFF + (size_t)t * E_;
            #pragma unroll
            for (int e = 0; e < E_; ++e) ep[e] = pr[e] * inv;
            float l2 = expf(m2 - m1);
            float gd = 1.f + l2;
            g_gate[t*2]     = 1.f / gd;
            g_gate[t*2 + 1] = l2 / gd;
            int pos = atomicAdd(&g_cnt[i1], 1); g_list[i1*MAXR + pos] = t*2;
            pos     = atomicAdd(&g_cnt[i2], 1); g_list[i2*MAXR + pos] = t*2 + 1;
        }
    }
}

// ---- fp16 mma.sync GEMM: 128 threads (4 warps, 2x2), tile BMx128, BK=32,
//      5-stage cp.async, 2 CTAs/SM. Warp tile (BM/2) x 64.
// MODE 0: final (A=g_ch, W=g_fwh, C=out,  K=2048, N=1024, BM=64)
// MODE 1: fc1   (A=g_xh by token, W=g_w1h, C=g_Hh fp16, K=1024, N=2048, relu, BM=128)
// MODE 2: fc2   (A=g_Hh by pair,  W=g_w2h, C=g_Y fp32,  K=2048, N=2048, *gate, BM=128)
#define NSTG 5

template<int MODE>
__global__ __launch_bounds__(128, 2) void mma_gemm(
        const float* __restrict__ biasF, float* __restrict__ Cout)
{
    constexpr int K    = (MODE == 1) ? 1024 : 2048;
    constexpr int NTOT = (MODE == 0) ? 1024 : 2048;
    constexpr int NC   = K / 32;
    constexpr int BM   = (MODE == 0) ? 64 : 128;
    constexpr int TA   = BM / 32;            // m16-tiles per warp: 2 or 4
    constexpr int CH_A = BM / 32;            // A 16B-chunks per thread: 2 or 4
    constexpr int ABYTES = BM * 64;
    constexpr int STG  = ABYTES + 128 * 64;  // stage bytes (A + B 8KB)

    const __half *Ah_g, *Wh_g;
    if (MODE == 0)      { Ah_g = g_ch;  Wh_g = g_fwh; }
    else if (MODE == 1) { Ah_g = g_xh;  Wh_g = g_w1h; }
    else                { Ah_g = g_Hh;  Wh_g = g_w2h; }

    int e = (MODE == 0) ? 0 : blockIdx.z;
    int cnt;
    const int* lst = nullptr;
    if (MODE == 0) cnt = B_;
    else { cnt = g_cnt[e]; lst = g_list + e * MAXR; }
    int row0 = blockIdx.y * BM;
    if (row0 >= cnt) return;
    int n0blk = blockIdx.x * 128;
    const __half* Wb = Wh_g + (size_t)e * NTOT * K;
    const float* bb = biasF + (size_t)e * ((MODE == 0) ? 0 : NTOT);

    extern __shared__ unsigned char sm[];
    uint32_t su = smem_u32(sm);

    int tid = threadIdx.x;
    int wid = tid >> 5, lane = tid & 31;
    int warp_m = wid >> 1;        // 0..1 (BM/2 rows each)
    int warp_n = wid & 1;         // 0..1 (64 cols each)

    // ---- cp.async assignment ----
    // A: BM rows x 4 chunks; BM=128 -> row=tid, chunks 0..3; BM=64 -> row=tid>>1, 2 chunks
    int r_a  = (BM == 128) ? tid : (tid >> 1);
    int ca0  = (BM == 128) ? 0 : ((tid & 1) * 2);
    int gr_ld = row0 + r_a;
    uint32_t aSz = (gr_ld < cnt) ? 16u : 0u;
    int aridx;
    if (MODE == 0) aridx = (gr_ld < cnt) ? gr_ld : 0;
    else {
        int p = (gr_ld < cnt) ? lst[gr_ld] : 0;
        aridx = (MODE == 1) ? (p >> 1) : p;
    }
    const __half* aP = Ah_g + (size_t)aridx * K;
    int sA[CH_A];
    #pragma unroll
    for (int j = 0; j < CH_A; ++j) sA[j] = swoff(r_a, ca0 + j);
    // B: 128 rows x 4 chunks; thread handles row tid, all 4 chunks
    const __half* bP = Wb + (size_t)(n0blk + tid) * K;
    int sB[4];
    #pragma unroll
    for (int j = 0; j < 4; ++j) sB[j] = swoff(tid, j);

    // ---- ldmatrix offsets ----
    int aoffs[TA][2], boffs[4][2];
    {
        int arr = warp_m * (BM/2) + (lane & 15);
        int achi = lane >> 4;
        #pragma unroll
        for (int t = 0; t < TA; ++t)
            #pragma unroll
            for (int ks = 0; ks < 2; ++ks)
                aoffs[t][ks] = swoff(arr + t * 16, ks * 2 + achi);
        int brr = warp_n * 64 + (lane & 7) + ((lane >> 4) << 3);
        int bchi = (lane >> 3) & 1;
        #pragma unroll
        for (int jj = 0; jj < 4; ++jj)
            #pragma unroll
            for (int ks = 0; ks < 2; ++ks)
                boffs[jj][ks] = swoff(brr + jj * 16, ks * 2 + bchi);
    }

    float acc[TA][8][4];
    #pragma unroll
    for (int t = 0; t < TA; ++t)
        #pragma unroll
        for (int j = 0; j < 8; ++j)
            #pragma unroll
            for (int q = 0; q < 4; ++q) acc[t][j][q] = 0.f;

    auto issue = [&](int c) {
        uint32_t sb = su + (c % NSTG) * STG;
        int k0 = c * 32;
        #pragma unroll
        for (int j = 0; j < CH_A; ++j)
            CPA16(sb + sA[j], aP + k0 + (ca0 + j) * 8, aSz);
        #pragma unroll
        for (int j = 0; j < 4; ++j)
            CPA16(sb + ABYTES + sB[j], bP + k0 + j * 8, 16u);
    };

    #pragma unroll
    for (int c = 0; c < NSTG - 1; ++c) { issue(c); CPCOMMIT(); }

    for (int c = 0; c < NC; ++c) {
        CPWAIT(NSTG - 2);
        __syncthreads();
        // exactly one commit per iteration (possibly empty near the tail)
        if (c + NSTG - 1 < NC) issue(c + NSTG - 1);
        CPCOMMIT();
        uint32_t base = su + (c % NSTG) * STG;
        #pragma unroll
        for (int ks = 0; ks < 2; ++ks) {
            uint32_t Af[TA][4], Bf[8][2];
            #pragma unroll
            for (int t = 0; t < TA; ++t)
                LDSM4(Af[t][0], Af[t][1], Af[t][2], Af[t][3], base + aoffs[t][ks]);
            #pragma unroll
            for (int jj = 0; jj < 4; ++jj)
                LDSM4(Bf[2*jj][0], Bf[2*jj][1], Bf[2*jj+1][0], Bf[2*jj+1][1],
                      base + ABYTES + boffs[jj][ks]);
            #pragma unroll
            for (int t = 0; t < TA; ++t)
                #pragma unroll
                for (int j = 0; j < 8; ++j)
                    MMA16816(acc[t][j], Af[t], Bf[j]);
        }
    }

    // ---- epilogue ----
    int mwarp = row0 + warp_m * (BM/2);
    #pragma unroll
    for (int t = 0; t < TA; ++t) {
        #pragma unroll
        for (int half = 0; half < 2; ++half) {
            int gr = mwarp + t * 16 + (lane >> 2) + half * 8;
            if (gr >= cnt) continue;
            float gate = 1.f;
            float* crowf = nullptr;
            __half* crh = nullptr;
            if (MODE == 0) crowf = Cout + (size_t)gr * O_;
            else {
                int p = lst[gr];
                if (MODE == 1) crh = g_Hh + (size_t)p * H_;
                else { crowf = g_Y + (size_t)p * H_; gate = g_gate[p]; }
            }
            #pragma unroll
            for (int j = 0; j < 8; ++j) {
                int n = n0blk + warp_n * 64 + j * 8 + (lane & 3) * 2;
                float v0 = acc[t][j][half*2 + 0] + bb[n];
                float v1 = acc[t][j][half*2 + 1] + bb[n + 1];
                if (MODE == 1) {
                    v0 = fmaxf(v0, 0.f); v1 = fmaxf(v1, 0.f);
                    __half2 hv = __floats2half2_rn(v0, v1);
                    *reinterpret_cast<uint32_t*>(crh + n) = *reinterpret_cast<uint32_t*>(&hv);
                } else {
                    if (MODE == 2) { v0 *= gate; v1 *= gate; }
                    *reinterpret_cast<float2*>(crowf + n) = make_float2(v0, v1);
                }
            }
        }
    }
}

// ---------------- combine: sum 4 pair rows, /S, to fp16 ----------------
__global__ void combine_kernel() {
    int idx = blockIdx.x * blockDim.x + threadIdx.x;
    int b  = idx >> 9;
    int gq = idx & 511;
    const float4* Y = reinterpret_cast<const float4*>(g_Y);
    size_t base0 = ((size_t)(b)      * 2) * (H_/4) + gq;
    size_t base1 = ((size_t)(B_ + b) * 2) * (H_/4) + gq;
    float4 y0 = Y[base0], y1 = Y[base0 + H_/4];
    float4 y2 = Y[base1], y3 = Y[base1 + H_/4];
    float4 o;
    o.x = 0.5f * (y0.x + y1.x + y2.x + y3.x);
    o.y = 0.5f * (y0.y + y1.y + y2.y + y3.y);
    o.z = 0.5f * (y0.z + y1.z + y2.z + y3.z);
    o.w = 0.5f * (y0.w + y1.w + y2.w + y3.w);
    __half2 a = __floats2half2_rn(o.x, o.y);
    __half2 c = __floats2half2_rn(o.z, o.w);
    uint2 pk;
    pk.x = *reinterpret_cast<uint32_t*>(&a);
    pk.y = *reinterpret_cast<uint32_t*>(&c);
    reinterpret_cast<uint2*>(g_ch)[(size_t)b * (H_/4) + gq] = pk;
}

extern "C" void kernel_launch(void* const* d_in, const int* in_sizes, int n_in,
                              void* d_out, int out_size) {
    const float* xs      = (const float*)d_in[0];
    const float* Wg      = (const float*)d_in[1];
    const float* b       = (const float*)d_in[2];
    const float* fc1_w   = (const float*)d_in[3];
    const float* fc1_b   = (const float*)d_in[4];
    const float* fc2_w   = (const float*)d_in[5];
    const float* fc2_b   = (const float*)d_in[6];
    const float* final_w = (const float*)d_in[7];
    const float* final_b = (const float*)d_in[8];
    float* out = (float*)d_out;

    constexpr int SMEM12 = NSTG * (128*64 + 128*64);  // 80 KB
    constexpr int SMEM0  = NSTG * ( 64*64 + 128*64);  // 60 KB
    cudaFuncSetAttribute(mma_gemm<0>, cudaFuncAttributeMaxDynamicSharedMemorySize, SMEM0);
    cudaFuncSetAttribute(mma_gemm<1>, cudaFuncAttributeMaxDynamicSharedMemorySize, SMEM12);
    cudaFuncSetAttribute(mma_gemm<2>, cudaFuncAttributeMaxDynamicSharedMemorySize, SMEM12);

    __half *xh, *w1h, *w2h, *fwh;
    cudaGetSymbolAddress((void**)&xh,  g_xh);
    cudaGetSymbolAddress((void**)&w1h, g_w1h);
    cudaGetSymbolAddress((void**)&w2h, g_w2h);
    cudaGetSymbolAddress((void**)&fwh, g_fwh);

    zero_kernel<<<1, 32>>>();
    gating_kernel<<<T_/64, 256>>>(xs, Wg, b, out);

    pack_half<<<(T_*D_/4)/256,    256>>>(xs,      xh,  T_*D_/4);
    pack_half<<<(E_*H_*D_/4)/256, 256>>>(fc1_w,   w1h, E_*H_*D_/4);
    pack_half<<<(E_*H_*H_/4)/256, 256>>>(fc2_w,   w2h, E_*H_*H_/4);
    pack_half<<<(O_*H_/4)/256,    256>>>(final_w, fwh, O_*H_/4);

    dim3 g1(H_/128, MAXR/128, E_);
    mma_gemm<1><<<g1, 128, SMEM12>>>(fc1_b, nullptr);
    mma_gemm<2><<<g1, 128, SMEM12>>>(fc2_b, nullptr);
    combine_kernel<<<(B_*(H_/4))/256, 256>>>();
    dim3 gf(O_/128, B_/64);
    mma_gemm<0><<<gf, 128, SMEM0>>>(final_b, out);
}

// round 11
// speedup vs baseline: 1.1337x; 1.1337x over previous
#include <cuda_runtime.h>
#include <cuda_bf16.h>
#include <cuda_fp16.h>
#include <math.h>
#include <stdint.h>

// Problem constants
#define S_ 2
#define B_ 2048
#define D_ 1024
#define H_ 2048
#define E_ 8
#define O_ 1024
#define T_ (S_*B_)        // 4096 tokens
#define P_ (T_*2)         // 8192 (token, k) pairs
#define MAXR 4096
#define OUT_OFF ((size_t)B_*O_)

// ---------------- scratch (device globals) ----------------
__device__ __align__(128) __half g_xh[(size_t)T_ * D_];
__device__ __align__(128) __half g_w1h[(size_t)E_ * H_ * D_];
__device__ __align__(128) __half g_w2h[(size_t)E_ * H_ * H_];
__device__ __align__(128) __half g_fwh[(size_t)O_ * H_];
__device__ __align__(128) __half g_Hh[(size_t)P_ * H_];
__device__ __align__(128) float  g_Y[(size_t)P_ * H_];
__device__ __align__(128) __half g_ch[(size_t)B_ * H_];
__device__ __align__(128) float g_gate[P_];
__device__ __align__(128) int   g_list[E_ * MAXR];
__device__ int   g_cnt[E_];

__device__ __forceinline__ uint32_t smem_u32(const void* p) {
    uint32_t a;
    asm("{ .reg .u64 t; cvta.to.shared.u64 t, %1; cvt.u32.u64 %0, t; }" : "=r"(a) : "l"(p));
    return a;
}

#define LDSM4(r0, r1, r2, r3, addr) \
    asm volatile("ldmatrix.sync.aligned.m8n8.x4.shared.b16 {%0,%1,%2,%3}, [%4];" \
        : "=r"(r0), "=r"(r1), "=r"(r2), "=r"(r3) : "r"(addr))

#define MMA16816(d, a, b) \
    asm volatile("mma.sync.aligned.m16n8k16.row.col.f32.f16.f16.f32 " \
        "{%0,%1,%2,%3}, {%4,%5,%6,%7}, {%8,%9}, {%0,%1,%2,%3};" \
        : "+f"((d)[0]), "+f"((d)[1]), "+f"((d)[2]), "+f"((d)[3]) \
        : "r"((a)[0]), "r"((a)[1]), "r"((a)[2]), "r"((a)[3]), \
          "r"((b)[0]), "r"((b)[1]))

#define CPA16(dst, src, sz) \
    asm volatile("cp.async.cg.shared.global [%0], [%1], 16, %2;" \
        :: "r"(dst), "l"(src), "r"(sz) : "memory")
#define CPCOMMIT() asm volatile("cp.async.commit_group;" ::: "memory")
#define CPWAIT(n)  asm volatile("cp.async.wait_group %0;" :: "n"(n) : "memory")

// swizzled byte offset within an N-row x 32-col fp16 plane (64B rows, 4x16B chunks)
__device__ __forceinline__ int swoff(int r, int c) {
    return r * 64 + ((c ^ ((r >> 1) & 3)) << 4);
}

__global__ void zero_kernel() {
    if (threadIdx.x < E_) g_cnt[threadIdx.x] = 0;
}

// ---------------- mega kernel: gating (+xs pack) and weight packs ----------------
#define GATE_BLKS 64
#define W1F4 (E_*H_*D_/4)   // 4194304
#define W2F4 (E_*H_*H_/4)   // 8388608
#define FWF4 (O_*H_/4)      // 524288
#define PACK_F4 (W1F4 + W2F4 + FWF4)
#define PACK_BLKS 6400

__global__ __launch_bounds__(256) void mega_kernel(
        const float* __restrict__ xs, const float* __restrict__ Wg,
        const float* __restrict__ bias,
        const float* __restrict__ w1, const float* __restrict__ w2,
        const float* __restrict__ fw, float* __restrict__ out)
{
    if (blockIdx.x >= GATE_BLKS) {
        // ---- weight pack: grid-stride over concatenated w1|w2|fw (float4 units) ----
        size_t base = (size_t)(blockIdx.x - GATE_BLKS) * 256 + threadIdx.x;
        size_t stride = (size_t)PACK_BLKS * 256;
        for (size_t i = base; i < (size_t)PACK_F4; i += stride) {
            size_t j = i;
            const float* s; __half* d;
            if (j < (size_t)W1F4) { s = w1; d = g_w1h; }
            else if ((j -= W1F4) < (size_t)W2F4) { s = w2; d = g_w2h; }
            else { j -= W2F4; s = fw; d = g_fwh; }
            float4 v = reinterpret_cast<const float4*>(s)[j];
            __half2 a = __floats2half2_rn(v.x, v.y);
            __half2 b = __floats2half2_rn(v.z, v.w);
            uint2 o;
            o.x = *reinterpret_cast<uint32_t*>(&a);
            o.y = *reinterpret_cast<uint32_t*>(&b);
            reinterpret_cast<uint2*>(d)[j] = o;
        }
        return;
    }
    // ---- gating + xs fp16 pack ----
    __shared__ __align__(16) float ws[E_][D_];
    int tid = threadIdx.x;
    for (int i = tid; i < E_*D_; i += 256) {
        int e = i >> 10, dd = i & (D_-1);
        ws[e][dd] = Wg[dd*E_ + e];
    }
    __syncthreads();
    int warp = tid >> 5, lane = tid & 31;
    for (int tt = 0; tt < 8; ++tt) {
        int t = blockIdx.x * 64 + warp * 8 + tt;
        float acc[E_];
        #pragma unroll
        for (int e = 0; e < E_; ++e) acc[e] = 0.f;
        const float4* xrow = reinterpret_cast<const float4*>(xs + (size_t)t * D_);
        uint2* xo = reinterpret_cast<uint2*>(g_xh + (size_t)t * D_);
        #pragma unroll
        for (int it = 0; it < D_/128; ++it) {
            float4 x = xrow[lane + it*32];
            // pack this quad to fp16
            {
                __half2 a = __floats2half2_rn(x.x, x.y);
                __half2 b = __floats2half2_rn(x.z, x.w);
                uint2 o;
                o.x = *reinterpret_cast<uint32_t*>(&a);
                o.y = *reinterpret_cast<uint32_t*>(&b);
                xo[lane + it*32] = o;
            }
            #pragma unroll
            for (int e = 0; e < E_; ++e) {
                float4 w = reinterpret_cast<const float4*>(ws[e])[lane + it*32];
                acc[e] += x.x*w.x + x.y*w.y + x.z*w.z + x.w*w.w;
            }
        }
        #pragma unroll
        for (int off = 16; off > 0; off >>= 1) {
            #pragma unroll
            for (int e = 0; e < E_; ++e)
                acc[e] += __shfl_xor_sync(0xffffffffu, acc[e], off);
        }
        if (lane == 0) {
            float h[E_];
            #pragma unroll
            for (int e = 0; e < E_; ++e) h[e] = acc[e] + bias[e];
            float m1 = h[0]; int i1 = 0;
            #pragma unroll
            for (int e = 1; e < E_; ++e) if (h[e] > m1) { m1 = h[e]; i1 = e; }
            float m2 = -3.0e38f; int i2 = 0;
            #pragma unroll
            for (int e = 0; e < E_; ++e) if (e != i1 && h[e] > m2) { m2 = h[e]; i2 = e; }
            float pr[E_]; float den = 0.f;
            #pragma unroll
            for (int e = 0; e < E_; ++e) { pr[e] = expf(h[e] - m1); den += pr[e]; }
            float inv = 1.f / den;
            float* ep = out + OUT_OFF + (size_t)t * E_;
            #pragma unroll
            for (int e = 0; e < E_; ++e) ep[e] = pr[e] * inv;
            float l2 = expf(m2 - m1);
            float gd = 1.f + l2;
            g_gate[t*2]     = 1.f / gd;
            g_gate[t*2 + 1] = l2 / gd;
            int pos = atomicAdd(&g_cnt[i1], 1); g_list[i1*MAXR + pos] = t*2;
            pos     = atomicAdd(&g_cnt[i2], 1); g_list[i2*MAXR + pos] = t*2 + 1;
        }
    }
}

// ---- fp16 mma.sync GEMM: 256 threads, tile 128x128, BK=32, 5-stage, 2 CTA/SM ----
// (round-7 configuration, race-free tail)
// Warp grid: 4 (m) x 2 (n); warp tile 32x64.
// MODE 0: final (A=g_ch, W=g_fwh, C=out,  K=2048, N=1024)
// MODE 1: fc1   (A=g_xh by token, W=g_w1h, C=g_Hh fp16, K=1024, N=2048, relu)
// MODE 2: fc2   (A=g_Hh by pair,  W=g_w2h, C=g_Y fp32,  K=2048, N=2048, *gate)
#define NSTG 5
#define STG_BYTES 16384       // A 8KB + B 8KB
#define GEMM_SMEM (NSTG * STG_BYTES)   // 80 KB

template<int MODE>
__global__ __launch_bounds__(256, 2) void mma_gemm(
        const float* __restrict__ biasF, float* __restrict__ Cout)
{
    constexpr int K    = (MODE == 1) ? 1024 : 2048;
    constexpr int NTOT = (MODE == 0) ? 1024 : 2048;
    constexpr int NC   = K / 32;

    const __half *Ah_g, *Wh_g;
    if (MODE == 0)      { Ah_g = g_ch;  Wh_g = g_fwh; }
    else if (MODE == 1) { Ah_g = g_xh;  Wh_g = g_w1h; }
    else                { Ah_g = g_Hh;  Wh_g = g_w2h; }

    int e = (MODE == 0) ? 0 : blockIdx.z;
    int cnt;
    const int* lst = nullptr;
    if (MODE == 0) cnt = B_;
    else { cnt = g_cnt[e]; lst = g_list + e * MAXR; }
    int row0 = blockIdx.y * 128;
    if (row0 >= cnt) return;
    int n0blk = blockIdx.x * 128;
    const __half* Wb = Wh_g + (size_t)e * NTOT * K;
    const float* bb = biasF + (size_t)e * ((MODE == 0) ? 0 : NTOT);

    extern __shared__ unsigned char sm[];
    uint32_t su = smem_u32(sm);

    int tid = threadIdx.x;
    int wid = tid >> 5, lane = tid & 31;
    int warp_m = wid >> 1;        // 0..3 (32 rows each)
    int warp_n = wid & 1;         // 0..1 (64 cols each)

    // ---- cp.async assignment: 2 A chunks + 2 B chunks per thread ----
    int r_ld = tid >> 1;                  // 0..127
    int c_ld = (tid & 1) * 2;             // 0 or 2
    int gr_ld = row0 + r_ld;
    uint32_t aSz = (gr_ld < cnt) ? 16u : 0u;
    int aridx;
    if (MODE == 0) aridx = (gr_ld < cnt) ? gr_ld : 0;
    else {
        int p = (gr_ld < cnt) ? lst[gr_ld] : 0;
        aridx = (MODE == 1) ? (p >> 1) : p;
    }
    const __half* aP = Ah_g + (size_t)aridx * K + c_ld * 8;
    const __half* bP = Wb + (size_t)(n0blk + r_ld) * K + c_ld * 8;
    int sA0 = swoff(r_ld, c_ld),     sA1 = swoff(r_ld, c_ld + 1);

    // ---- ldmatrix offsets ----
    int aoffs[2][2], boffs[4][2];
    {
        int arr = warp_m * 32 + (lane & 15);
        int achi = lane >> 4;
        #pragma unroll
        for (int t = 0; t < 2; ++t)
            #pragma unroll
            for (int ks = 0; ks < 2; ++ks)
                aoffs[t][ks] = swoff(arr + t * 16, ks * 2 + achi);
        int brr = warp_n * 64 + (lane & 7) + ((lane >> 4) << 3);
        int bchi = (lane >> 3) & 1;
        #pragma unroll
        for (int jj = 0; jj < 4; ++jj)
            #pragma unroll
            for (int ks = 0; ks < 2; ++ks)
                boffs[jj][ks] = swoff(brr + jj * 16, ks * 2 + bchi);
    }

    float acc[2][8][4];
    #pragma unroll
    for (int t = 0; t < 2; ++t)
        #pragma unroll
        for (int j = 0; j < 8; ++j)
            #pragma unroll
            for (int q = 0; q < 4; ++q) acc[t][j][q] = 0.f;

    auto issue = [&](int c) {
        uint32_t sb = su + (c % NSTG) * STG_BYTES;
        int k0 = c * 32;
        CPA16(sb + sA0, aP + k0, aSz);
        CPA16(sb + sA1, aP + k0 + 8, aSz);
        CPA16(sb + 8192 + sA0, bP + k0, 16u);
        CPA16(sb + 8192 + sA1, bP + k0 + 8, 16u);
    };

    #pragma unroll
    for (int c = 0; c < NSTG - 1; ++c) { issue(c); CPCOMMIT(); }

    for (int c = 0; c < NC; ++c) {
        CPWAIT(NSTG - 2);
        __syncthreads();
        // exactly one commit per iteration (possibly empty near tail) — keeps
        // wait_group(NSTG-2) a valid guarantee for stage c
        if (c + NSTG - 1 < NC) issue(c + NSTG - 1);
        CPCOMMIT();
        uint32_t base = su + (c % NSTG) * STG_BYTES;
        #pragma unroll
        for (int ks = 0; ks < 2; ++ks) {
            uint32_t Af[2][4], Bf[8][2];
            #pragma unroll
            for (int t = 0; t < 2; ++t)
                LDSM4(Af[t][0], Af[t][1], Af[t][2], Af[t][3], base + aoffs[t][ks]);
            #pragma unroll
            for (int jj = 0; jj < 4; ++jj)
                LDSM4(Bf[2*jj][0], Bf[2*jj][1], Bf[2*jj+1][0], Bf[2*jj+1][1],
                      base + 8192 + boffs[jj][ks]);
            #pragma unroll
            for (int t = 0; t < 2; ++t)
                #pragma unroll
                for (int j = 0; j < 8; ++j)
                    MMA16816(acc[t][j], Af[t], Bf[j]);
        }
    }

    // ---- epilogue ----
    int mwarp = row0 + warp_m * 32;
    #pragma unroll
    for (int t = 0; t < 2; ++t) {
        #pragma unroll
        for (int half = 0; half < 2; ++half) {
            int gr = mwarp + t * 16 + (lane >> 2) + half * 8;
            if (gr >= cnt) continue;
            float gate = 1.f;
            float* crowf = nullptr;
            __half* crh = nullptr;
            if (MODE == 0) crowf = Cout + (size_t)gr * O_;
            else {
                int p = lst[gr];
                if (MODE == 1) crh = g_Hh + (size_t)p * H_;
                else { crowf = g_Y + (size_t)p * H_; gate = g_gate[p]; }
            }
            #pragma unroll
            for (int j = 0; j < 8; ++j) {
                int n = n0blk + warp_n * 64 + j * 8 + (lane & 3) * 2;
                float v0 = acc[t][j][half*2 + 0] + bb[n];
                float v1 = acc[t][j][half*2 + 1] + bb[n + 1];
                if (MODE == 1) {
                    v0 = fmaxf(v0, 0.f); v1 = fmaxf(v1, 0.f);
                    __half2 hv = __floats2half2_rn(v0, v1);
                    *reinterpret_cast<uint32_t*>(crh + n) = *reinterpret_cast<uint32_t*>(&hv);
                } else {
                    if (MODE == 2) { v0 *= gate; v1 *= gate; }
                    *reinterpret_cast<float2*>(crowf + n) = make_float2(v0, v1);
                }
            }
        }
    }
}

// ---------------- combine: sum 4 pair rows, /S, to fp16 ----------------
__global__ void combine_kernel() {
    int idx = blockIdx.x * blockDim.x + threadIdx.x;
    int b  = idx >> 9;
    int gq = idx & 511;
    const float4* Y = reinterpret_cast<const float4*>(g_Y);
    size_t base0 = ((size_t)(b)      * 2) * (H_/4) + gq;
    size_t base1 = ((size_t)(B_ + b) * 2) * (H_/4) + gq;
    float4 y0 = Y[base0], y1 = Y[base0 + H_/4];
    float4 y2 = Y[base1], y3 = Y[base1 + H_/4];
    float4 o;
    o.x = 0.5f * (y0.x + y1.x + y2.x + y3.x);
    o.y = 0.5f * (y0.y + y1.y + y2.y + y3.y);
    o.z = 0.5f * (y0.z + y1.z + y2.z + y3.z);
    o.w = 0.5f * (y0.w + y1.w + y2.w + y3.w);
    __half2 a = __floats2half2_rn(o.x, o.y);
    __half2 c = __floats2half2_rn(o.z, o.w);
    uint2 pk;
    pk.x = *reinterpret_cast<uint32_t*>(&a);
    pk.y = *reinterpret_cast<uint32_t*>(&c);
    reinterpret_cast<uint2*>(g_ch)[(size_t)b * (H_/4) + gq] = pk;
}

extern "C" void kernel_launch(void* const* d_in, const int* in_sizes, int n_in,
                              void* d_out, int out_size) {
    const float* xs      = (const float*)d_in[0];
    const float* Wg      = (const float*)d_in[1];
    const float* b       = (const float*)d_in[2];
    const float* fc1_w   = (const float*)d_in[3];
    const float* fc1_b   = (const float*)d_in[4];
    const float* fc2_w   = (const float*)d_in[5];
    const float* fc2_b   = (const float*)d_in[6];
    const float* final_w = (const float*)d_in[7];
    const float* final_b = (const float*)d_in[8];
    float* out = (float*)d_out;

    cudaFuncSetAttribute(mma_gemm<0>, cudaFuncAttributeMaxDynamicSharedMemorySize, GEMM_SMEM);
    cudaFuncSetAttribute(mma_gemm<1>, cudaFuncAttributeMaxDynamicSharedMemorySize, GEMM_SMEM);
    cudaFuncSetAttribute(mma_gemm<2>, cudaFuncAttributeMaxDynamicSharedMemorySize, GEMM_SMEM);

    zero_kernel<<<1, 32>>>();
    mega_kernel<<<GATE_BLKS + PACK_BLKS, 256>>>(xs, Wg, b, fc1_w, fc2_w, final_w, out);

    dim3 g1(H_/128, MAXR/128, E_);
    mma_gemm<1><<<g1, 256, GEMM_SMEM>>>(fc1_b, nullptr);
    mma_gemm<2><<<g1, 256, GEMM_SMEM>>>(fc2_b, nullptr);
    combine_kernel<<<(B_*(H_/4))/256, 256>>>();
    dim3 gf(O_/128, B_/128);
    mma_gemm<0><<<gf, 256, GEMM_SMEM>>>(final_b, out);
}

// round 13
// speedup vs baseline: 1.4107x; 1.2443x over previous
#include <cuda_runtime.h>
#include <cuda_bf16.h>
#include <cuda_fp16.h>
#include <math.h>
#include <stdint.h>

// Problem constants
#define S_ 2
#define B_ 2048
#define D_ 1024
#define H_ 2048
#define E_ 8
#define O_ 1024
#define T_ (S_*B_)        // 4096 tokens
#define P_ (T_*2)         // 8192 (token, k) pairs
#define MAXR 4096
#define OUT_OFF ((size_t)B_*O_)

// ---------------- scratch (device globals) ----------------
__device__ __align__(128) __half g_xh[(size_t)T_ * D_];
__device__ __align__(128) __half g_w1h[(size_t)E_ * H_ * D_];
__device__ __align__(128) __half g_w2h[(size_t)E_ * H_ * H_];
__device__ __align__(128) __half g_fwh[(size_t)O_ * H_];
__device__ __align__(128) __half g_Hh[(size_t)P_ * H_];
__device__ __align__(128) float  g_Y[(size_t)P_ * H_];
__device__ __align__(128) __half g_ch[(size_t)B_ * H_];
__device__ __align__(128) float g_gate[P_];
__device__ __align__(128) int   g_list[E_ * MAXR];
__device__ int   g_cnt[E_];

__device__ __forceinline__ uint32_t smem_u32(const void* p) {
    uint32_t a;
    asm("{ .reg .u64 t; cvta.to.shared.u64 t, %1; cvt.u32.u64 %0, t; }" : "=r"(a) : "l"(p));
    return a;
}

#define LDSM4(r0, r1, r2, r3, addr) \
    asm volatile("ldmatrix.sync.aligned.m8n8.x4.shared.b16 {%0,%1,%2,%3}, [%4];" \
        : "=r"(r0), "=r"(r1), "=r"(r2), "=r"(r3) : "r"(addr))

#define MMA16816(d, a, b) \
    asm volatile("mma.sync.aligned.m16n8k16.row.col.f32.f16.f16.f32 " \
        "{%0,%1,%2,%3}, {%4,%5,%6,%7}, {%8,%9}, {%0,%1,%2,%3};" \
        : "+f"((d)[0]), "+f"((d)[1]), "+f"((d)[2]), "+f"((d)[3]) \
        : "r"((a)[0]), "r"((a)[1]), "r"((a)[2]), "r"((a)[3]), \
          "r"((b)[0]), "r"((b)[1]))

#define CPA16(dst, src, sz) \
    asm volatile("cp.async.cg.shared.global [%0], [%1], 16, %2;" \
        :: "r"(dst), "l"(src), "r"(sz) : "memory")
#define CPCOMMIT() asm volatile("cp.async.commit_group;" ::: "memory")
#define CPWAIT(n)  asm volatile("cp.async.wait_group %0;" :: "n"(n) : "memory")

// swizzled byte offset within an N-row x 32-col fp16 plane (64B rows, 4x16B chunks)
__device__ __forceinline__ int swoff(int r, int c) {
    return r * 64 + ((c ^ ((r >> 1) & 3)) << 4);
}

__global__ void zero_kernel() {
    if (threadIdx.x < E_) g_cnt[threadIdx.x] = 0;
}

// ---------------- fused pack: xs|w1|w2|fw -> fp16, pure grid-stride ----------------
#define XSF4 (T_*D_/4)      // 1048576
#define W1F4 (E_*H_*D_/4)   // 4194304
#define W2F4 (E_*H_*H_/4)   // 8388608
#define FWF4 (O_*H_/4)      // 524288
#define PACK_F4 (XSF4 + W1F4 + W2F4 + FWF4)
#define PACK_BLKS 3552      // 24 blocks/SM x 148

__global__ __launch_bounds__(256) void pack_all(
        const float* __restrict__ xs, const float* __restrict__ w1,
        const float* __restrict__ w2, const float* __restrict__ fw)
{
    size_t i0 = (size_t)blockIdx.x * 256 + threadIdx.x;
    size_t stride = (size_t)PACK_BLKS * 256;
    for (size_t i = i0; i < (size_t)PACK_F4; i += stride) {
        size_t j = i;
        const float* s; __half* d;
        if (j < (size_t)XSF4) { s = xs; d = g_xh; }
        else if ((j -= XSF4) < (size_t)W1F4) { s = w1; d = g_w1h; }
        else if ((j -= W1F4) < (size_t)W2F4) { s = w2; d = g_w2h; }
        else { j -= W2F4; s = fw; d = g_fwh; }
        float4 v = reinterpret_cast<const float4*>(s)[j];
        __half2 a = __floats2half2_rn(v.x, v.y);
        __half2 b = __floats2half2_rn(v.z, v.w);
        uint2 o;
        o.x = *reinterpret_cast<uint32_t*>(&a);
        o.y = *reinterpret_cast<uint32_t*>(&b);
        reinterpret_cast<uint2*>(d)[j] = o;
    }
}

// ---------------- gating ----------------
__global__ __launch_bounds__(256) void gating_kernel(
        const float* __restrict__ xs, const float* __restrict__ Wg,
        const float* __restrict__ bias, float* __restrict__ out)
{
    __shared__ __align__(16) float ws[E_][D_];
    int tid = threadIdx.x;
    for (int i = tid; i < E_*D_; i += 256) {
        int e = i >> 10, d = i & (D_-1);
        ws[e][d] = Wg[d*E_ + e];
    }
    __syncthreads();
    int warp = tid >> 5, lane = tid & 31;
    for (int tt = 0; tt < 8; ++tt) {
        int t = blockIdx.x * 64 + warp * 8 + tt;
        float acc[E_];
        #pragma unroll
        for (int e = 0; e < E_; ++e) acc[e] = 0.f;
        const float4* xrow = reinterpret_cast<const float4*>(xs + (size_t)t * D_);
        #pragma unroll
        for (int it = 0; it < D_/128; ++it) {
            float4 x = xrow[lane + it*32];
            #pragma unroll
            for (int e = 0; e < E_; ++e) {
                float4 w = reinterpret_cast<const float4*>(ws[e])[lane + it*32];
                acc[e] += x.x*w.x + x.y*w.y + x.z*w.z + x.w*w.w;
            }
        }
        #pragma unroll
        for (int off = 16; off > 0; off >>= 1) {
            #pragma unroll
            for (int e = 0; e < E_; ++e)
                acc[e] += __shfl_xor_sync(0xffffffffu, acc[e], off);
        }
        if (lane == 0) {
            float h[E_];
            #pragma unroll
            for (int e = 0; e < E_; ++e) h[e] = acc[e] + bias[e];
            float m1 = h[0]; int i1 = 0;
            #pragma unroll
            for (int e = 1; e < E_; ++e) if (h[e] > m1) { m1 = h[e]; i1 = e; }
            float m2 = -3.0e38f; int i2 = 0;
            #pragma unroll
            for (int e = 0; e < E_; ++e) if (e != i1 && h[e] > m2) { m2 = h[e]; i2 = e; }
            float pr[E_]; float den = 0.f;
            #pragma unroll
            for (int e = 0; e < E_; ++e) { pr[e] = expf(h[e] - m1); den += pr[e]; }
            float inv = 1.f / den;
            float* ep = out + OUT_OFF + (size_t)t * E_;
            #pragma unroll
            for (int e = 0; e < E_; ++e) ep[e] = pr[e] * inv;
            float l2 = expf(m2 - m1);
            float gd = 1.f + l2;
            g_gate[t*2]     = 1.f / gd;
            g_gate[t*2 + 1] = l2 / gd;
            int pos = atomicAdd(&g_cnt[i1], 1); g_list[i1*MAXR + pos] = t*2;
            pos     = atomicAdd(&g_cnt[i2], 1); g_list[i2*MAXR + pos] = t*2 + 1;
        }
    }
}

// ---- fp16 mma.sync GEMM: 256 threads, tile 128x128, BK=32, 6-stage, 2 CTA/SM ----
// Warp grid: 4 (m) x 2 (n); warp tile 32x64. (round-7 shape, race-free tail)
// MODE 0: final (A=g_ch, W=g_fwh, C=out,  K=2048, N=1024)
// MODE 1: fc1   (A=g_xh by token, W=g_w1h, C=g_Hh fp16, K=1024, N=2048, relu)
// MODE 2: fc2   (A=g_Hh by pair,  W=g_w2h, C=g_Y fp32,  K=2048, N=2048, *gate)
#define NSTG 6
#define STG_BYTES 16384       // A 8KB + B 8KB
#define GEMM_SMEM (NSTG * STG_BYTES)   // 96 KB

template<int MODE>
__global__ __launch_bounds__(256, 2) void mma_gemm(
        const float* __restrict__ biasF, float* __restrict__ Cout)
{
    constexpr int K    = (MODE == 1) ? 1024 : 2048;
    constexpr int NTOT = (MODE == 0) ? 1024 : 2048;
    constexpr int NC   = K / 32;

    const __half *Ah_g, *Wh_g;
    if (MODE == 0)      { Ah_g = g_ch;  Wh_g = g_fwh; }
    else if (MODE == 1) { Ah_g = g_xh;  Wh_g = g_w1h; }
    else                { Ah_g = g_Hh;  Wh_g = g_w2h; }

    int e = (MODE == 0) ? 0 : blockIdx.z;
    int cnt;
    const int* lst = nullptr;
    if (MODE == 0) cnt = B_;
    else { cnt = g_cnt[e]; lst = g_list + e * MAXR; }
    int row0 = blockIdx.y * 128;
    if (row0 >= cnt) return;
    int n0blk = blockIdx.x * 128;
    const __half* Wb = Wh_g + (size_t)e * NTOT * K;
    const float* bb = biasF + (size_t)e * ((MODE == 0) ? 0 : NTOT);

    extern __shared__ unsigned char sm[];
    uint32_t su = smem_u32(sm);

    int tid = threadIdx.x;
    int wid = tid >> 5, lane = tid & 31;
    int warp_m = wid >> 1;        // 0..3 (32 rows each)
    int warp_n = wid & 1;         // 0..1 (64 cols each)

    // ---- cp.async assignment: 2 A chunks + 2 B chunks per thread ----
    int r_ld = tid >> 1;                  // 0..127
    int c_ld = (tid & 1) * 2;             // 0 or 2
    int gr_ld = row0 + r_ld;
    uint32_t aSz = (gr_ld < cnt) ? 16u : 0u;
    int aridx;
    if (MODE == 0) aridx = (gr_ld < cnt) ? gr_ld : 0;
    else {
        int p = (gr_ld < cnt) ? lst[gr_ld] : 0;
        aridx = (MODE == 1) ? (p >> 1) : p;
    }
    const __half* aP = Ah_g + (size_t)aridx * K + c_ld * 8;
    const __half* bP = Wb + (size_t)(n0blk + r_ld) * K + c_ld * 8;
    int sA0 = swoff(r_ld, c_ld),     sA1 = swoff(r_ld, c_ld + 1);

    // ---- ldmatrix offsets ----
    int aoffs[2][2], boffs[4][2];
    {
        int arr = warp_m * 32 + (lane & 15);
        int achi = lane >> 4;
        #pragma unroll
        for (int t = 0; t < 2; ++t)
            #pragma unroll
            for (int ks = 0; ks < 2; ++ks)
                aoffs[t][ks] = swoff(arr + t * 16, ks * 2 + achi);
        int brr = warp_n * 64 + (lane & 7) + ((lane >> 4) << 3);
        int bchi = (lane >> 3) & 1;
        #pragma unroll
        for (int jj = 0; jj < 4; ++jj)
            #pragma unroll
            for (int ks = 0; ks < 2; ++ks)
                boffs[jj][ks] = swoff(brr + jj * 16, ks * 2 + bchi);
    }

    float acc[2][8][4];
    #pragma unroll
    for (int t = 0; t < 2; ++t)
        #pragma unroll
        for (int j = 0; j < 8; ++j)
            #pragma unroll
            for (int q = 0; q < 4; ++q) acc[t][j][q] = 0.f;

    auto issue = [&](int c) {
        uint32_t sb = su + (c % NSTG) * STG_BYTES;
        int k0 = c * 32;
        CPA16(sb + sA0, aP + k0, aSz);
        CPA16(sb + sA1, aP + k0 + 8, aSz);
        CPA16(sb + 8192 + sA0, bP + k0, 16u);
        CPA16(sb + 8192 + sA1, bP + k0 + 8, 16u);
    };

    #pragma unroll
    for (int c = 0; c < NSTG - 1; ++c) { issue(c); CPCOMMIT(); }

    for (int c = 0; c < NC; ++c) {
        CPWAIT(NSTG - 2);
        __syncthreads();
        // exactly one commit per iteration (possibly empty near tail) — keeps
        // wait_group(NSTG-2) a valid guarantee for stage c
        if (c + NSTG - 1 < NC) issue(c + NSTG - 1);
        CPCOMMIT();
        uint32_t base = su + (c % NSTG) * STG_BYTES;
        #pragma unroll
        for (int ks = 0; ks < 2; ++ks) {
            uint32_t Af[2][4], Bf[8][2];
            #pragma unroll
            for (int t = 0; t < 2; ++t)
                LDSM4(Af[t][0], Af[t][1], Af[t][2], Af[t][3], base + aoffs[t][ks]);
            #pragma unroll
            for (int jj = 0; jj < 4; ++jj)
                LDSM4(Bf[2*jj][0], Bf[2*jj][1], Bf[2*jj+1][0], Bf[2*jj+1][1],
                      base + 8192 + boffs[jj][ks]);
            #pragma unroll
            for (int t = 0; t < 2; ++t)
                #pragma unroll
                for (int j = 0; j < 8; ++j)
                    MMA16816(acc[t][j], Af[t], Bf[j]);
        }
    }

    // ---- epilogue ----
    int mwarp = row0 + warp_m * 32;
    #pragma unroll
    for (int t = 0; t < 2; ++t) {
        #pragma unroll
        for (int half = 0; half < 2; ++half) {
            int gr = mwarp + t * 16 + (lane >> 2) + half * 8;
            if (gr >= cnt) continue;
            float gate = 1.f;
            float* crowf = nullptr;
            __half* crh = nullptr;
            if (MODE == 0) crowf = Cout + (size_t)gr * O_;
            else {
                int p = lst[gr];
                if (MODE == 1) crh = g_Hh + (size_t)p * H_;
                else { crowf = g_Y + (size_t)p * H_; gate = g_gate[p]; }
            }
            #pragma unroll
            for (int j = 0; j < 8; ++j) {
                int n = n0blk + warp_n * 64 + j * 8 + (lane & 3) * 2;
                float v0 = acc[t][j][half*2 + 0] + bb[n];
                float v1 = acc[t][j][half*2 + 1] + bb[n + 1];
                if (MODE == 1) {
                    v0 = fmaxf(v0, 0.f); v1 = fmaxf(v1, 0.f);
                    __half2 hv = __floats2half2_rn(v0, v1);
                    *reinterpret_cast<uint32_t*>(crh + n) = *reinterpret_cast<uint32_t*>(&hv);
                } else {
                    if (MODE == 2) { v0 *= gate; v1 *= gate; }
                    *reinterpret_cast<float2*>(crowf + n) = make_float2(v0, v1);
                }
            }
        }
    }
}

// ---------------- combine: sum 4 pair rows, /S, to fp16 ----------------
__global__ void combine_kernel() {
    int idx = blockIdx.x * blockDim.x + threadIdx.x;
    int b  = idx >> 9;
    int gq = idx & 511;
    const float4* Y = reinterpret_cast<const float4*>(g_Y);
    size_t base0 = ((size_t)(b)      * 2) * (H_/4) + gq;
    size_t base1 = ((size_t)(B_ + b) * 2) * (H_/4) + gq;
    float4 y0 = Y[base0], y1 = Y[base0 + H_/4];
    float4 y2 = Y[base1], y3 = Y[base1 + H_/4];
    float4 o;
    o.x = 0.5f * (y0.x + y1.x + y2.x + y3.x);
    o.y = 0.5f * (y0.y + y1.y + y2.y + y3.y);
    o.z = 0.5f * (y0.z + y1.z + y2.z + y3.z);
    o.w = 0.5f * (y0.w + y1.w + y2.w + y3.w);
    __half2 a = __floats2half2_rn(o.x, o.y);
    __half2 c = __floats2half2_rn(o.z, o.w);
    uint2 pk;
    pk.x = *reinterpret_cast<uint32_t*>(&a);
    pk.y = *reinterpret_cast<uint32_t*>(&c);
    reinterpret_cast<uint2*>(g_ch)[(size_t)b * (H_/4) + gq] = pk;
}

extern "C" void kernel_launch(void* const* d_in, const int* in_sizes, int n_in,
                              void* d_out, int out_size) {
    const float* xs      = (const float*)d_in[0];
    const float* Wg      = (const float*)d_in[1];
    const float* b       = (const float*)d_in[2];
    const float* fc1_w   = (const float*)d_in[3];
    const float* fc1_b   = (const float*)d_in[4];
    const float* fc2_w   = (const float*)d_in[5];
    const float* fc2_b   = (const float*)d_in[6];
    const float* final_w = (const float*)d_in[7];
    const float* final_b = (const float*)d_in[8];
    float* out = (float*)d_out;

    cudaFuncSetAttribute(mma_gemm<0>, cudaFuncAttributeMaxDynamicSharedMemorySize, GEMM_SMEM);
    cudaFuncSetAttribute(mma_gemm<1>, cudaFuncAttributeMaxDynamicSharedMemorySize, GEMM_SMEM);
    cudaFuncSetAttribute(mma_gemm<2>, cudaFuncAttributeMaxDynamicSharedMemorySize, GEMM_SMEM);

    zero_kernel<<<1, 32>>>();
    gating_kernel<<<T_/64, 256>>>(xs, Wg, b, out);
    pack_all<<<PACK_BLKS, 256>>>(xs, fc1_w, fc2_w, final_w);

    dim3 g1(H_/128, MAXR/128, E_);
    mma_gemm<1><<<g1, 256, GEMM_SMEM>>>(fc1_b, nullptr);
    mma_gemm<2><<<g1, 256, GEMM_SMEM>>>(fc2_b, nullptr);
    combine_kernel<<<(B_*(H_/4))/256, 256>>>();
    dim3 gf(O_/128, B_/128);
    mma_gemm<0><<<gf, 256, GEMM_SMEM>>>(final_b, out);
}

// round 14
// speedup vs baseline: 1.4513x; 1.0288x over previous
#include <cuda_runtime.h>
#include <cuda_bf16.h>
#include <cuda_fp16.h>
#include <math.h>
#include <stdint.h>

// Problem constants
#define S_ 2
#define B_ 2048
#define D_ 1024
#define H_ 2048
#define E_ 8
#define O_ 1024
#define T_ (S_*B_)        // 4096 tokens
#define P_ (T_*2)         // 8192 (token, k) pairs
#define MAXR 4096
#define OUT_OFF ((size_t)B_*O_)

// ---------------- scratch (device globals) ----------------
__device__ __align__(128) __half g_xh[(size_t)T_ * D_];
__device__ __align__(128) __half g_w1h[(size_t)E_ * H_ * D_];
__device__ __align__(128) __half g_w2h[(size_t)E_ * H_ * H_];
__device__ __align__(128) __half g_fwh[(size_t)O_ * H_];
__device__ __align__(128) __half g_Hh[(size_t)P_ * H_];
__device__ __align__(128) float  g_Y[(size_t)P_ * H_];
__device__ __align__(128) __half g_ch[(size_t)B_ * H_];
__device__ __align__(128) float g_gate[P_];
__device__ __align__(128) int   g_list[E_ * MAXR];
__device__ int   g_cnt[E_];

__device__ __forceinline__ uint32_t smem_u32(const void* p) {
    uint32_t a;
    asm("{ .reg .u64 t; cvta.to.shared.u64 t, %1; cvt.u32.u64 %0, t; }" : "=r"(a) : "l"(p));
    return a;
}

#define LDSM4(r0, r1, r2, r3, addr) \
    asm volatile("ldmatrix.sync.aligned.m8n8.x4.shared.b16 {%0,%1,%2,%3}, [%4];" \
        : "=r"(r0), "=r"(r1), "=r"(r2), "=r"(r3) : "r"(addr))

#define MMA16816(d, a, b) \
    asm volatile("mma.sync.aligned.m16n8k16.row.col.f32.f16.f16.f32 " \
        "{%0,%1,%2,%3}, {%4,%5,%6,%7}, {%8,%9}, {%0,%1,%2,%3};" \
        : "+f"((d)[0]), "+f"((d)[1]), "+f"((d)[2]), "+f"((d)[3]) \
        : "r"((a)[0]), "r"((a)[1]), "r"((a)[2]), "r"((a)[3]), \
          "r"((b)[0]), "r"((b)[1]))

#define CPA16(dst, src, sz) \
    asm volatile("cp.async.cg.shared.global [%0], [%1], 16, %2;" \
        :: "r"(dst), "l"(src), "r"(sz) : "memory")
#define CPCOMMIT() asm volatile("cp.async.commit_group;" ::: "memory")
#define CPWAIT(n)  asm volatile("cp.async.wait_group %0;" :: "n"(n) : "memory")

// swizzled byte offset within an N-row x 32-col fp16 plane (64B rows, 4x16B chunks)
__device__ __forceinline__ int swoff(int r, int c) {
    return r * 64 + ((c ^ ((r >> 1) & 3)) << 4);
}

__global__ void zero_kernel() {
    if (threadIdx.x < E_) g_cnt[threadIdx.x] = 0;
}

// ---------------- fused pack: xs|w1|w2|fw -> fp16, branch-free region loops ----------------
#define XSF4 (T_*D_/4)      // 1048576
#define W1F4 (E_*H_*D_/4)   // 4194304
#define W2F4 (E_*H_*H_/4)   // 8388608
#define FWF4 (O_*H_/4)      // 524288
#define PACK_BLKS 3552      // 24 blocks/SM x 148

__device__ __forceinline__ void pack_loop(const float* __restrict__ s,
                                          __half* __restrict__ d,
                                          size_t n4, size_t i0, size_t stride) {
    for (size_t j = i0; j < n4; j += stride) {
        float4 v = reinterpret_cast<const float4*>(s)[j];
        __half2 a = __floats2half2_rn(v.x, v.y);
        __half2 b = __floats2half2_rn(v.z, v.w);
        uint2 o;
        o.x = *reinterpret_cast<uint32_t*>(&a);
        o.y = *reinterpret_cast<uint32_t*>(&b);
        reinterpret_cast<uint2*>(d)[j] = o;
    }
}

__global__ __launch_bounds__(256) void pack_all(
        const float* __restrict__ xs, const float* __restrict__ w1,
        const float* __restrict__ w2, const float* __restrict__ fw)
{
    size_t i0 = (size_t)blockIdx.x * 256 + threadIdx.x;
    size_t stride = (size_t)PACK_BLKS * 256;
    pack_loop(xs, g_xh,  XSF4, i0, stride);
    pack_loop(w1, g_w1h, W1F4, i0, stride);
    pack_loop(w2, g_w2h, W2F4, i0, stride);
    pack_loop(fw, g_fwh, FWF4, i0, stride);
}

// ---------------- gating: 256 blocks x 16 tokens ----------------
__global__ __launch_bounds__(256) void gating_kernel(
        const float* __restrict__ xs, const float* __restrict__ Wg,
        const float* __restrict__ bias, float* __restrict__ out)
{
    __shared__ __align__(16) float ws[E_][D_];
    int tid = threadIdx.x;
    for (int i = tid; i < E_*D_; i += 256) {
        int e = i >> 10, d = i & (D_-1);
        ws[e][d] = Wg[d*E_ + e];
    }
    __syncthreads();
    int warp = tid >> 5, lane = tid & 31;
    for (int tt = 0; tt < 2; ++tt) {
        int t = blockIdx.x * 16 + warp * 2 + tt;
        float acc[E_];
        #pragma unroll
        for (int e = 0; e < E_; ++e) acc[e] = 0.f;
        const float4* xrow = reinterpret_cast<const float4*>(xs + (size_t)t * D_);
        #pragma unroll
        for (int it = 0; it < D_/128; ++it) {
            float4 x = xrow[lane + it*32];
            #pragma unroll
            for (int e = 0; e < E_; ++e) {
                float4 w = reinterpret_cast<const float4*>(ws[e])[lane + it*32];
                acc[e] += x.x*w.x + x.y*w.y + x.z*w.z + x.w*w.w;
            }
        }
        #pragma unroll
        for (int off = 16; off > 0; off >>= 1) {
            #pragma unroll
            for (int e = 0; e < E_; ++e)
                acc[e] += __shfl_xor_sync(0xffffffffu, acc[e], off);
        }
        if (lane == 0) {
            float h[E_];
            #pragma unroll
            for (int e = 0; e < E_; ++e) h[e] = acc[e] + bias[e];
            float m1 = h[0]; int i1 = 0;
            #pragma unroll
            for (int e = 1; e < E_; ++e) if (h[e] > m1) { m1 = h[e]; i1 = e; }
            float m2 = -3.0e38f; int i2 = 0;
            #pragma unroll
            for (int e = 0; e < E_; ++e) if (e != i1 && h[e] > m2) { m2 = h[e]; i2 = e; }
            float pr[E_]; float den = 0.f;
            #pragma unroll
            for (int e = 0; e < E_; ++e) { pr[e] = expf(h[e] - m1); den += pr[e]; }
            float inv = 1.f / den;
            float* ep = out + OUT_OFF + (size_t)t * E_;
            #pragma unroll
            for (int e = 0; e < E_; ++e) ep[e] = pr[e] * inv;
            float l2 = expf(m2 - m1);
            float gd = 1.f + l2;
            g_gate[t*2]     = 1.f / gd;
            g_gate[t*2 + 1] = l2 / gd;
            int pos = atomicAdd(&g_cnt[i1], 1); g_list[i1*MAXR + pos] = t*2;
            pos     = atomicAdd(&g_cnt[i2], 1); g_list[i2*MAXR + pos] = t*2 + 1;
        }
    }
}

// ---- fp16 mma.sync GEMM: 256 threads, tile BMx128, BK=32, 6-stage, 2 CTA/SM ----
// Warp grid: 4 (m) x 2 (n); warp tile (BM/4) x 64.
// MODE 0: final (A=g_ch, W=g_fwh, C=out,  K=2048, N=1024, BM=64)
// MODE 1: fc1   (A=g_xh by token, W=g_w1h, C=g_Hh fp16, K=1024, N=2048, relu, BM=128)
// MODE 2: fc2   (A=g_Hh by pair,  W=g_w2h, C=g_Y fp32,  K=2048, N=2048, *gate, BM=128)
#define NSTG 6

template<int MODE>
__global__ __launch_bounds__(256, 2) void mma_gemm(
        const float* __restrict__ biasF, float* __restrict__ Cout)
{
    constexpr int K    = (MODE == 1) ? 1024 : 2048;
    constexpr int NTOT = (MODE == 0) ? 1024 : 2048;
    constexpr int NC   = K / 32;
    constexpr int BM   = (MODE == 0) ? 64 : 128;
    constexpr int TA   = BM / 64;            // m16 tiles per warp: 1 or 2
    constexpr int TPR  = 256 / BM;           // threads per A row: 4 or 2
    constexpr int CHT  = 4 / TPR;            // A chunks per thread: 1 or 2
    constexpr int ABYTES = BM * 64;
    constexpr int STG  = ABYTES + 128 * 64;

    const __half *Ah_g, *Wh_g;
    if (MODE == 0)      { Ah_g = g_ch;  Wh_g = g_fwh; }
    else if (MODE == 1) { Ah_g = g_xh;  Wh_g = g_w1h; }
    else                { Ah_g = g_Hh;  Wh_g = g_w2h; }

    int e = (MODE == 0) ? 0 : blockIdx.z;
    int cnt;
    const int* lst = nullptr;
    if (MODE == 0) cnt = B_;
    else { cnt = g_cnt[e]; lst = g_list + e * MAXR; }
    int row0 = blockIdx.y * BM;
    if (row0 >= cnt) return;
    int n0blk = blockIdx.x * 128;
    const __half* Wb = Wh_g + (size_t)e * NTOT * K;
    const float* bb = biasF + (size_t)e * ((MODE == 0) ? 0 : NTOT);

    extern __shared__ unsigned char sm[];
    uint32_t su = smem_u32(sm);

    int tid = threadIdx.x;
    int wid = tid >> 5, lane = tid & 31;
    int warp_m = wid >> 1;        // 0..3 (BM/4 rows each)
    int warp_n = wid & 1;         // 0..1 (64 cols each)

    // ---- cp.async assignment ----
    int r_ld = tid / TPR;                 // 0..BM-1
    int c0   = (tid % TPR) * CHT;         // starting chunk
    int gr_ld = row0 + r_ld;
    uint32_t aSz = (gr_ld < cnt) ? 16u : 0u;
    int aridx;
    if (MODE == 0) aridx = (gr_ld < cnt) ? gr_ld : 0;
    else {
        int p = (gr_ld < cnt) ? lst[gr_ld] : 0;
        aridx = (MODE == 1) ? (p >> 1) : p;
    }
    const __half* aP = Ah_g + (size_t)aridx * K;
    int sA[CHT];
    #pragma unroll
    for (int j = 0; j < CHT; ++j) sA[j] = swoff(r_ld, c0 + j);
    // B: 128 rows x 4 chunks; thread tid>>1 handles row, 2 chunks at (tid&1)*2
    int rb = tid >> 1, cb = (tid & 1) * 2;
    const __half* bP = Wb + (size_t)(n0blk + rb) * K;
    int sB0 = swoff(rb, cb), sB1 = swoff(rb, cb + 1);

    // ---- ldmatrix offsets ----
    int aoffs[TA][2], boffs[4][2];
    {
        int arr = warp_m * (BM/4) + (lane & 15);
        int achi = lane >> 4;
        #pragma unroll
        for (int t = 0; t < TA; ++t)
            #pragma unroll
            for (int ks = 0; ks < 2; ++ks)
                aoffs[t][ks] = swoff(arr + t * 16, ks * 2 + achi);
        int brr = warp_n * 64 + (lane & 7) + ((lane >> 4) << 3);
        int bchi = (lane >> 3) & 1;
        #pragma unroll
        for (int jj = 0; jj < 4; ++jj)
            #pragma unroll
            for (int ks = 0; ks < 2; ++ks)
                boffs[jj][ks] = swoff(brr + jj * 16, ks * 2 + bchi);
    }

    float acc[TA][8][4];
    #pragma unroll
    for (int t = 0; t < TA; ++t)
        #pragma unroll
        for (int j = 0; j < 8; ++j)
            #pragma unroll
            for (int q = 0; q < 4; ++q) acc[t][j][q] = 0.f;

    auto issue = [&](int c) {
        uint32_t sb = su + (c % NSTG) * STG;
        int k0 = c * 32;
        #pragma unroll
        for (int j = 0; j < CHT; ++j)
            CPA16(sb + sA[j], aP + k0 + (c0 + j) * 8, aSz);
        CPA16(sb + ABYTES + sB0, bP + k0 + cb * 8, 16u);
        CPA16(sb + ABYTES + sB1, bP + k0 + (cb + 1) * 8, 16u);
    };

    #pragma unroll
    for (int c = 0; c < NSTG - 1; ++c) { issue(c); CPCOMMIT(); }

    for (int c = 0; c < NC; ++c) {
        CPWAIT(NSTG - 2);
        __syncthreads();
        // exactly one commit per iteration (possibly empty near tail)
        if (c + NSTG - 1 < NC) issue(c + NSTG - 1);
        CPCOMMIT();
        uint32_t base = su + (c % NSTG) * STG;
        #pragma unroll
        for (int ks = 0; ks < 2; ++ks) {
            uint32_t Af[TA][4], Bf[8][2];
            #pragma unroll
            for (int t = 0; t < TA; ++t)
                LDSM4(Af[t][0], Af[t][1], Af[t][2], Af[t][3], base + aoffs[t][ks]);
            #pragma unroll
            for (int jj = 0; jj < 4; ++jj)
                LDSM4(Bf[2*jj][0], Bf[2*jj][1], Bf[2*jj+1][0], Bf[2*jj+1][1],
                      base + ABYTES + boffs[jj][ks]);
            #pragma unroll
            for (int t = 0; t < TA; ++t)
                #pragma unroll
                for (int j = 0; j < 8; ++j)
                    MMA16816(acc[t][j], Af[t], Bf[j]);
        }
    }

    // ---- epilogue ----
    int mwarp = row0 + warp_m * (BM/4);
    #pragma unroll
    for (int t = 0; t < TA; ++t) {
        #pragma unroll
        for (int half = 0; half < 2; ++half) {
            int gr = mwarp + t * 16 + (lane >> 2) + half * 8;
            if (gr >= cnt) continue;
            float gate = 1.f;
            float* crowf = nullptr;
            __half* crh = nullptr;
            if (MODE == 0) crowf = Cout + (size_t)gr * O_;
            else {
                int p = lst[gr];
                if (MODE == 1) crh = g_Hh + (size_t)p * H_;
                else { crowf = g_Y + (size_t)p * H_; gate = g_gate[p]; }
            }
            #pragma unroll
            for (int j = 0; j < 8; ++j) {
                int n = n0blk + warp_n * 64 + j * 8 + (lane & 3) * 2;
                float v0 = acc[t][j][half*2 + 0] + bb[n];
                float v1 = acc[t][j][half*2 + 1] + bb[n + 1];
                if (MODE == 1) {
                    v0 = fmaxf(v0, 0.f); v1 = fmaxf(v1, 0.f);
                    __half2 hv = __floats2half2_rn(v0, v1);
                    *reinterpret_cast<uint32_t*>(crh + n) = *reinterpret_cast<uint32_t*>(&hv);
                } else {
                    if (MODE == 2) { v0 *= gate; v1 *= gate; }
                    *reinterpret_cast<float2*>(crowf + n) = make_float2(v0, v1);
                }
            }
        }
    }
}

// ---------------- combine: sum 4 pair rows, /S, to fp16 ----------------
__global__ void combine_kernel() {
    int idx = blockIdx.x * blockDim.x + threadIdx.x;
    int b  = idx >> 9;
    int gq = idx & 511;
    const float4* Y = reinterpret_cast<const float4*>(g_Y);
    size_t base0 = ((size_t)(b)      * 2) * (H_/4) + gq;
    size_t base1 = ((size_t)(B_ + b) * 2) * (H_/4) + gq;
    float4 y0 = Y[base0], y1 = Y[base0 + H_/4];
    float4 y2 = Y[base1], y3 = Y[base1 + H_/4];
    float4 o;
    o.x = 0.5f * (y0.x + y1.x + y2.x + y3.x);
    o.y = 0.5f * (y0.y + y1.y + y2.y + y3.y);
    o.z = 0.5f * (y0.z + y1.z + y2.z + y3.z);
    o.w = 0.5f * (y0.w + y1.w + y2.w + y3.w);
    __half2 a = __floats2half2_rn(o.x, o.y);
    __half2 c = __floats2half2_rn(o.z, o.w);
    uint2 pk;
    pk.x = *reinterpret_cast<uint32_t*>(&a);
    pk.y = *reinterpret_cast<uint32_t*>(&c);
    reinterpret_cast<uint2*>(g_ch)[(size_t)b * (H_/4) + gq] = pk;
}

extern "C" void kernel_launch(void* const* d_in, const int* in_sizes, int n_in,
                              void* d_out, int out_size) {
    const float* xs      = (const float*)d_in[0];
    const float* Wg      = (const float*)d_in[1];
    const float* b       = (const float*)d_in[2];
    const float* fc1_w   = (const float*)d_in[3];
    const float* fc1_b   = (const float*)d_in[4];
    const float* fc2_w   = (const float*)d_in[5];
    const float* fc2_b   = (const float*)d_in[6];
    const float* final_w = (const float*)d_in[7];
    const float* final_b = (const float*)d_in[8];
    float* out = (float*)d_out;

    constexpr int SMEM12 = NSTG * (128*64 + 128*64);  // 96 KB
    constexpr int SMEM0  = NSTG * ( 64*64 + 128*64);  // 72 KB
    cudaFuncSetAttribute(mma_gemm<0>, cudaFuncAttributeMaxDynamicSharedMemorySize, SMEM0);
    cudaFuncSetAttribute(mma_gemm<1>, cudaFuncAttributeMaxDynamicSharedMemorySize, SMEM12);
    cudaFuncSetAttribute(mma_gemm<2>, cudaFuncAttributeMaxDynamicSharedMemorySize, SMEM12);

    zero_kernel<<<1, 32>>>();
    gating_kernel<<<T_/16, 256>>>(xs, Wg, b, out);
    pack_all<<<PACK_BLKS, 256>>>(xs, fc1_w, fc2_w, final_w);

    dim3 g1(H_/128, MAXR/128, E_);
    mma_gemm<1><<<g1, 256, SMEM12>>>(fc1_b, nullptr);
    mma_gemm<2><<<g1, 256, SMEM12>>>(fc2_b, nullptr);
    combine_kernel<<<(B_*(H_/4))/256, 256>>>();
    dim3 gf(O_/128, B_/64);
    mma_gemm<0><<<gf, 256, SMEM0>>>(final_b, out);
}